// round 1
// baseline (speedup 1.0000x reference)
#include <cuda_runtime.h>
#include <math.h>

#define Bdim 2
#define Ldim 2048
#define Sdim 2048
#define Edim 1024
#define Hn   16
#define Dh   64
#define Mrows 4096   // B*L = B*S

// Scratch (module-load allocated, allowed)
__device__ float g_Q[(size_t)Mrows * Edim];
__device__ float g_K[(size_t)Mrows * Edim];
__device__ float g_V[(size_t)Mrows * Edim];
__device__ float g_O[(size_t)Mrows * Edim];

// ---------------------------------------------------------------------------
// SGEMM + bias: C[M,N] = A[M,K] @ W[K,N] + bias[N]
// 128x128 block tile, BK=8, 256 threads, 8x8 per-thread microtile.
// ---------------------------------------------------------------------------
__global__ __launch_bounds__(256) void sgemm_bias_kernel(
    const float* __restrict__ A, const float* __restrict__ W,
    const float* __restrict__ bias, float* __restrict__ C,
    int M, int N, int K)
{
    __shared__ float As[8][128];   // transposed A tile: As[k][m]
    __shared__ float Bs[8][128];   // Bs[k][n]

    const int tid = threadIdx.x;
    const int tx = tid & 15;       // 0..15 -> 8 output cols each
    const int ty = tid >> 4;       // 0..15 -> 8 output rows each
    const int row0 = blockIdx.y * 128;
    const int col0 = blockIdx.x * 128;

    // A tile load mapping: 128 rows x 8 k, float4 along k
    const int ar = tid >> 1;
    const int ak = (tid & 1) << 2;
    // B tile load mapping: 8 k x 128 n, float4 along n
    const int br = tid >> 5;
    const int bn = (tid & 31) << 2;

    const float* Apt = A + (size_t)(row0 + ar) * K + ak;
    const float* Wpt = W + (size_t)br * N + col0 + bn;

    float acc[8][8];
    #pragma unroll
    for (int i = 0; i < 8; i++)
        #pragma unroll
        for (int j = 0; j < 8; j++) acc[i][j] = 0.0f;

    float4 av = *(const float4*)(Apt);
    float4 wv = *(const float4*)(Wpt);

    for (int k0 = 0; k0 < K; k0 += 8) {
        As[ak + 0][ar] = av.x;
        As[ak + 1][ar] = av.y;
        As[ak + 2][ar] = av.z;
        As[ak + 3][ar] = av.w;
        *(float4*)&Bs[br][bn] = wv;
        __syncthreads();

        if (k0 + 8 < K) {   // prefetch next tile (overlap LDG with compute)
            av = *(const float4*)(Apt + k0 + 8);
            wv = *(const float4*)(Wpt + (size_t)(k0 + 8) * N);
        }

        #pragma unroll
        for (int kk = 0; kk < 8; kk++) {
            float4 a0 = *(const float4*)&As[kk][ty * 8];
            float4 a1 = *(const float4*)&As[kk][ty * 8 + 4];
            float4 b0 = *(const float4*)&Bs[kk][tx * 8];
            float4 b1 = *(const float4*)&Bs[kk][tx * 8 + 4];
            float aa[8] = {a0.x, a0.y, a0.z, a0.w, a1.x, a1.y, a1.z, a1.w};
            float bb[8] = {b0.x, b0.y, b0.z, b0.w, b1.x, b1.y, b1.z, b1.w};
            #pragma unroll
            for (int i = 0; i < 8; i++)
                #pragma unroll
                for (int j = 0; j < 8; j++)
                    acc[i][j] = fmaf(aa[i], bb[j], acc[i][j]);
        }
        __syncthreads();
    }

    // Epilogue with bias, float4 stores
    #pragma unroll
    for (int i = 0; i < 8; i++) {
        const size_t row = (size_t)(row0 + ty * 8 + i);
        float* Cp = C + row * N + col0 + tx * 8;
        const float* bp = bias + col0 + tx * 8;
        float4 o0, o1;
        o0.x = acc[i][0] + bp[0]; o0.y = acc[i][1] + bp[1];
        o0.z = acc[i][2] + bp[2]; o0.w = acc[i][3] + bp[3];
        o1.x = acc[i][4] + bp[4]; o1.y = acc[i][5] + bp[5];
        o1.z = acc[i][6] + bp[6]; o1.w = acc[i][7] + bp[7];
        *(float4*)(Cp)     = o0;
        *(float4*)(Cp + 4) = o1;
    }
}

// ---------------------------------------------------------------------------
// Flash attention (fp32). One block per (b, h, 64-row query tile).
// 256 threads = 16x16, 4x4 microtile over 64x64 score / output tiles.
// S processed in chunks of 64 with online softmax.
// Smem: exactly 48KB static. KPT holds K^T during scores, P^T during PV.
// Swizzle (4-float groups): slot(row, e) = row*64 + (((e>>2)^(row&15))<<2 | (e&3))
// ---------------------------------------------------------------------------
__global__ __launch_bounds__(256) void attn_kernel(
    const float* __restrict__ Q, const float* __restrict__ K,
    const float* __restrict__ V, float* __restrict__ O)
{
    __shared__ float QT[64 * 64];   // Q^T swizzled: buffer-row = d, elem = r
    __shared__ float KPT[64 * 64];  // K^T (row=d, elem=s) then P^T (row=s, elem=r)
    __shared__ float Vs[64 * 64];   // V direct [s][d]

    const int tid = threadIdx.x;
    const int tx = tid & 15;
    const int ty = tid >> 4;

    const int lt = blockIdx.x & 31;          // query tile within L (L/64 = 32)
    const int h  = (blockIdx.x >> 5) & 15;
    const int b  = blockIdx.x >> 9;

    const float* Qbase = Q + ((size_t)(b * Ldim + lt * 64)) * Edim + h * Dh;
    const float* Kbase = K + (size_t)b * Sdim * Edim + h * Dh;
    const float* Vbase = V + (size_t)b * Sdim * Edim + h * Dh;

    // Load Q tile transposed + swizzled
    for (int idx = tid; idx < 4096; idx += 256) {
        const int r = idx >> 6, d = idx & 63;
        QT[d * 64 + ((((r >> 2) ^ (d & 15)) << 2) | (r & 3))] =
            Qbase[(size_t)r * Edim + d];
    }

    float m_state[4], l_state[4], acc[4][4];
    #pragma unroll
    for (int i = 0; i < 4; i++) {
        m_state[i] = -1e30f;
        l_state[i] = 0.0f;
        #pragma unroll
        for (int j = 0; j < 4; j++) acc[i][j] = 0.0f;
    }

    const float scale = 0.125f;   // 1/sqrt(64)

    for (int sc = 0; sc < Sdim / 64; sc++) {
        const float* Kc = Kbase + (size_t)sc * 64 * Edim;
        const float* Vc = Vbase + (size_t)sc * 64 * Edim;

        __syncthreads();   // prior PV reads of KPT/Vs done (also covers Q load, sc=0)
        for (int idx = tid; idx < 4096; idx += 256) {
            const int s = idx >> 6, d = idx & 63;
            KPT[d * 64 + ((((s >> 2) ^ (d & 15)) << 2) | (s & 3))] =
                Kc[(size_t)s * Edim + d];
            Vs[idx] = Vc[(size_t)s * Edim + d];
        }
        __syncthreads();

        // ---- scores: s[i][j] = sum_d Q[r][d] * K[c][d], r=ty*4+i, c=tx*4+j
        float p[4][4];
        #pragma unroll
        for (int i = 0; i < 4; i++)
            #pragma unroll
            for (int j = 0; j < 4; j++) p[i][j] = 0.0f;

        #pragma unroll 4
        for (int d = 0; d < 64; d++) {
            float4 aq = *(const float4*)&QT[d * 64 + ((ty ^ (d & 15)) << 2)];
            float4 bk = *(const float4*)&KPT[d * 64 + ((tx ^ (d & 15)) << 2)];
            float aa[4] = {aq.x, aq.y, aq.z, aq.w};
            float bb[4] = {bk.x, bk.y, bk.z, bk.w};
            #pragma unroll
            for (int i = 0; i < 4; i++)
                #pragma unroll
                for (int j = 0; j < 4; j++)
                    p[i][j] = fmaf(aa[i], bb[j], p[i][j]);
        }

        __syncthreads();   // all KT reads done before overwriting KPT with P^T

        // ---- online softmax per query row (reduce across 16-lane tx groups)
        #pragma unroll
        for (int i = 0; i < 4; i++) {
            float t0 = p[i][0] * scale, t1 = p[i][1] * scale;
            float t2 = p[i][2] * scale, t3 = p[i][3] * scale;
            float mx = fmaxf(fmaxf(t0, t1), fmaxf(t2, t3));
            #pragma unroll
            for (int o = 8; o >= 1; o >>= 1)
                mx = fmaxf(mx, __shfl_xor_sync(0xffffffffu, mx, o));
            const float m_new = fmaxf(m_state[i], mx);
            const float corr = __expf(m_state[i] - m_new);
            t0 = __expf(t0 - m_new); t1 = __expf(t1 - m_new);
            t2 = __expf(t2 - m_new); t3 = __expf(t3 - m_new);
            float rs = t0 + t1 + t2 + t3;
            #pragma unroll
            for (int o = 8; o >= 1; o >>= 1)
                rs += __shfl_xor_sync(0xffffffffu, rs, o);
            l_state[i] = l_state[i] * corr + rs;
            m_state[i] = m_new;
            #pragma unroll
            for (int j = 0; j < 4; j++) acc[i][j] *= corr;
            p[i][0] = t0; p[i][1] = t1; p[i][2] = t2; p[i][3] = t3;
        }

        // write P^T into KPT: buffer-row = c (s index), elem = r
        #pragma unroll
        for (int j = 0; j < 4; j++) {
            const int c = tx * 4 + j;
            #pragma unroll
            for (int i = 0; i < 4; i++)
                KPT[c * 64 + (((ty ^ (c & 15)) << 2) | i)] = p[i][j];
        }
        __syncthreads();

        // ---- PV: acc[i][j] += sum_s P[r][s] * V[s][d], d = tx*4+j
        #pragma unroll 4
        for (int s = 0; s < 64; s++) {
            float4 ap = *(const float4*)&KPT[s * 64 + ((ty ^ (s & 15)) << 2)];
            float4 bv = *(const float4*)&Vs[s * 64 + tx * 4];
            float aa[4] = {ap.x, ap.y, ap.z, ap.w};
            float bb[4] = {bv.x, bv.y, bv.z, bv.w};
            #pragma unroll
            for (int i = 0; i < 4; i++)
                #pragma unroll
                for (int j = 0; j < 4; j++)
                    acc[i][j] = fmaf(aa[i], bb[j], acc[i][j]);
        }
    }

    // Epilogue: normalize and store to O[(b*L + r)][h*64 + d]
    #pragma unroll
    for (int i = 0; i < 4; i++) {
        const float inv = 1.0f / l_state[i];
        const int r = lt * 64 + ty * 4 + i;
        float4 o;
        o.x = acc[i][0] * inv; o.y = acc[i][1] * inv;
        o.z = acc[i][2] * inv; o.w = acc[i][3] * inv;
        *(float4*)(O + ((size_t)(b * Ldim + r)) * Edim + h * Dh + tx * 4) = o;
    }
}

// ---------------------------------------------------------------------------
extern "C" void kernel_launch(void* const* d_in, const int* in_sizes, int n_in,
                              void* d_out, int out_size)
{
    const float* x   = (const float*)d_in[0];
    const float* ctx = (const float*)d_in[1];
    const float* Wq  = (const float*)d_in[2];
    const float* bq  = (const float*)d_in[3];
    const float* Wk  = (const float*)d_in[4];
    const float* bk  = (const float*)d_in[5];
    const float* Wv  = (const float*)d_in[6];
    const float* bv  = (const float*)d_in[7];
    const float* Wp  = (const float*)d_in[8];
    const float* bp  = (const float*)d_in[9];
    float* out = (float*)d_out;

    float *Qb, *Kb, *Vb, *Ob;
    cudaGetSymbolAddress((void**)&Qb, g_Q);
    cudaGetSymbolAddress((void**)&Kb, g_K);
    cudaGetSymbolAddress((void**)&Vb, g_V);
    cudaGetSymbolAddress((void**)&Ob, g_O);

    dim3 gemm_grid(Edim / 128, Mrows / 128);

    sgemm_bias_kernel<<<gemm_grid, 256>>>(x,   Wq, bq, Qb, Mrows, Edim, Edim);
    sgemm_bias_kernel<<<gemm_grid, 256>>>(ctx, Wk, bk, Kb, Mrows, Edim, Edim);
    sgemm_bias_kernel<<<gemm_grid, 256>>>(ctx, Wv, bv, Vb, Mrows, Edim, Edim);

    attn_kernel<<<Bdim * Hn * (Ldim / 64), 256>>>(Qb, Kb, Vb, Ob);

    sgemm_bias_kernel<<<gemm_grid, 256>>>(Ob, Wp, bp, out, Mrows, Edim, Edim);
}

// round 3
// speedup vs baseline: 1.2723x; 1.2723x over previous
#include <cuda_runtime.h>
#include <cuda_bf16.h>
#include <math.h>
#include <stdint.h>

#define Bdim 2
#define Ldim 2048
#define Sdim 2048
#define Edim 1024
#define Hn   16
#define Dh   64
#define Mrows 4096   // B*L = B*S

#define GM Mrows
#define GN Edim
#define GK Edim

// GEMM tiling
#define BM 128
#define BN 128
#define BK 64
#define CHUNKS (GK / BK)      // 16

// Scratch (module-load allocated, allowed)
__device__ float g_Q[(size_t)Mrows * Edim];
__device__ float g_K[(size_t)Mrows * Edim];
__device__ float g_V[(size_t)Mrows * Edim];
__device__ float g_O[(size_t)Mrows * Edim];

// ---------------------------------------------------------------------------
// helpers
// ---------------------------------------------------------------------------
__device__ __forceinline__ uint32_t smem_u32(const void* p) {
    uint32_t a;
    asm("{ .reg .u64 t; cvta.to.shared.u64 t, %1; cvt.u32.u64 %0, t; }"
        : "=r"(a) : "l"(p));
    return a;
}

__device__ __forceinline__ void ldsm4(uint32_t* r, uint32_t addr) {
    asm volatile("ldmatrix.sync.aligned.m8n8.x4.shared.b16 {%0,%1,%2,%3}, [%4];"
                 : "=r"(r[0]), "=r"(r[1]), "=r"(r[2]), "=r"(r[3]) : "r"(addr));
}
__device__ __forceinline__ void ldsm4t(uint32_t* r, uint32_t addr) {
    asm volatile("ldmatrix.sync.aligned.m8n8.x4.trans.shared.b16 {%0,%1,%2,%3}, [%4];"
                 : "=r"(r[0]), "=r"(r[1]), "=r"(r[2]), "=r"(r[3]) : "r"(addr));
}

__device__ __forceinline__ void mma16816(float* d, const uint32_t* a, const uint32_t* b) {
    asm volatile(
        "mma.sync.aligned.m16n8k16.row.col.f32.bf16.bf16.f32 "
        "{%0,%1,%2,%3}, {%4,%5,%6,%7}, {%8,%9}, {%0,%1,%2,%3};"
        : "+f"(d[0]), "+f"(d[1]), "+f"(d[2]), "+f"(d[3])
        : "r"(a[0]), "r"(a[1]), "r"(a[2]), "r"(a[3]), "r"(b[0]), "r"(b[1]));
}

// split float pair into bf16 hi (packed) + lo floats
__device__ __forceinline__ uint32_t split_pack_hi(float a, float b, float& la, float& lb) {
    __nv_bfloat16 ha = __float2bfloat16_rn(a);
    __nv_bfloat16 hb = __float2bfloat16_rn(b);
    la = a - __bfloat162float(ha);
    lb = b - __bfloat162float(hb);
    return ((uint32_t)__bfloat16_as_ushort(hb) << 16) | (uint32_t)__bfloat16_as_ushort(ha);
}
__device__ __forceinline__ uint32_t pack_bf16(float a, float b) {
    __nv_bfloat16 ha = __float2bfloat16_rn(a);
    __nv_bfloat16 hb = __float2bfloat16_rn(b);
    return ((uint32_t)__bfloat16_as_ushort(hb) << 16) | (uint32_t)__bfloat16_as_ushort(ha);
}

// swizzles: A rows are 128B (XOR row bits 7-9 into byte bits 4-6),
//           B rows are 256B (XOR row bits 8-10 into byte bits 4-6)
__device__ __forceinline__ uint32_t sw_a(uint32_t off) { return off ^ ((off >> 3) & 0x70); }
__device__ __forceinline__ uint32_t sw_b(uint32_t off) { return off ^ ((off >> 4) & 0x70); }

// SMEM stage layout: A_hi 16K | A_lo 16K | B_hi 16K | B_lo 16K = 64K, x2 stages
#define A_HI_OFF    0
#define A_LO_OFF    16384
#define B_HI_OFF    32768
#define B_LO_OFF    49152
#define STAGE_BYTES 65536
#define GEMM_SMEM_TOTAL (2 * STAGE_BYTES)   // 131072

// ---------------------------------------------------------------------------
// bf16x3 mma.sync GEMM + bias: C[GM,GN] = A[GM,GK] @ W[GK,GN] + bias
// 512 threads (16 warps, 4x4 warp grid, 32x32 warp tiles), 128x128 CTA tile.
// A tile: [m(128)][k(64)] bf16. B tile: [k(64)][n(128)] bf16.
// ---------------------------------------------------------------------------
__global__ __launch_bounds__(512, 1) void gemm_tc_kernel(
    const float* __restrict__ A, const float* __restrict__ W,
    const float* __restrict__ bias, float* __restrict__ C)
{
    extern __shared__ char smem[];
    const uint32_t smem_base = smem_u32(smem);

    const int tid    = threadIdx.x;
    const int wid    = tid >> 5;
    const int lane   = tid & 31;
    const int warp_m = wid & 3;        // *32 rows
    const int warp_n = wid >> 2;       // *32 cols
    const int row0   = blockIdx.y * BM;
    const int col0   = blockIdx.x * BN;

    const int sub = lane >> 3;         // ldmatrix sub-tile
    const int lr  = lane & 7;

    // precomputed ldmatrix smem offsets (per ks added later)
    // A: row = warp_m*32 + mt*16 + (sub&1)*8 + lr ; kb = ks*32 + (sub>>1)*16
    const int a_row_base = warp_m * 32 + (sub & 1) * 8 + lr;
    const int a_kb_base  = (sub >> 1) * 16;
    // B: k = ks*16 + (sub&1)*8 + lr ; nb = (warp_n*32 + (jn + (sub>>1))*8)*2
    const int b_k_base  = (sub & 1) * 8 + lr;
    const int b_nb_base = (warp_n * 32 + (sub >> 1) * 8) * 2;

    float acc[2][4][4];   // [mt][nt][frag]
    #pragma unroll
    for (int mt = 0; mt < 2; mt++)
        #pragma unroll
        for (int nt = 0; nt < 4; nt++)
            #pragma unroll
            for (int q = 0; q < 4; q++) acc[mt][nt][q] = 0.0f;

    // ---- global load mapping
    // A: idx = i*512+tid; r = idx>>4 (0..127), c4 = idx&15 (float4 along k)
    // B: idx = i*512+tid; kr = idx>>5 (0..63), n4 = idx&31 (float4 along n)
    float4 avr[4], bvr[4];

    // prologue: load + store chunk 0 into stage 0
    {
        #pragma unroll
        for (int i = 0; i < 4; i++) {
            int idx = i * 512 + tid;
            int r = idx >> 4, c4 = idx & 15;
            avr[i] = *(const float4*)(A + (size_t)(row0 + r) * GK + c4 * 4);
            int kr = idx >> 5, n4 = idx & 31;
            bvr[i] = *(const float4*)(W + (size_t)kr * GN + col0 + n4 * 4);
        }
        char* stg = smem;
        #pragma unroll
        for (int i = 0; i < 4; i++) {
            int idx = i * 512 + tid;
            {
                int r = idx >> 4, c4 = idx & 15;
                float lx, ly, lz, lw;
                uint32_t h01 = split_pack_hi(avr[i].x, avr[i].y, lx, ly);
                uint32_t h23 = split_pack_hi(avr[i].z, avr[i].w, lz, lw);
                uint32_t off = sw_a((uint32_t)(r * 128 + c4 * 8));
                *(uint2*)(stg + A_HI_OFF + off) = make_uint2(h01, h23);
                *(uint2*)(stg + A_LO_OFF + off) = make_uint2(pack_bf16(lx, ly), pack_bf16(lz, lw));
            }
            {
                int kr = idx >> 5, n4 = idx & 31;
                float lx, ly, lz, lw;
                uint32_t h01 = split_pack_hi(bvr[i].x, bvr[i].y, lx, ly);
                uint32_t h23 = split_pack_hi(bvr[i].z, bvr[i].w, lz, lw);
                uint32_t off = sw_b((uint32_t)(kr * 256 + n4 * 8));
                *(uint2*)(stg + B_HI_OFF + off) = make_uint2(h01, h23);
                *(uint2*)(stg + B_LO_OFF + off) = make_uint2(pack_bf16(lx, ly), pack_bf16(lz, lw));
            }
        }
    }

    for (int c = 0; c < CHUNKS; c++) {
        const int st = c & 1;
        const uint32_t a_base = smem_base + st * STAGE_BYTES;
        const uint32_t b_base = a_base + B_HI_OFF;

        __syncthreads();   // chunk c stores visible; stage st^1 reads (iter c-1) done

        // issue LDG for chunk c+1 (latency hidden under mma)
        if (c + 1 < CHUNKS) {
            const int k0n = (c + 1) * BK;
            #pragma unroll
            for (int i = 0; i < 4; i++) {
                int idx = i * 512 + tid;
                int r = idx >> 4, c4 = idx & 15;
                avr[i] = *(const float4*)(A + (size_t)(row0 + r) * GK + k0n + c4 * 4);
                int kr = idx >> 5, n4 = idx & 31;
                bvr[i] = *(const float4*)(W + (size_t)(k0n + kr) * GN + col0 + n4 * 4);
            }
        }

        // ---- mma over 4 k16 steps
        #pragma unroll
        for (int ks = 0; ks < 4; ks++) {
            uint32_t ahi[2][4], alo[2][4];
            #pragma unroll
            for (int mt = 0; mt < 2; mt++) {
                uint32_t off = sw_a((uint32_t)((a_row_base + mt * 16) * 128 + ks * 32 + a_kb_base));
                ldsm4(ahi[mt], a_base + A_HI_OFF + off);
                ldsm4(alo[mt], a_base + (A_LO_OFF - A_HI_OFF) + A_HI_OFF + off);  // A_LO
            }
            #pragma unroll
            for (int jn = 0; jn < 4; jn += 2) {
                uint32_t bhi[4], blo[4];
                uint32_t off = sw_b((uint32_t)((ks * 16 + b_k_base) * 256 + b_nb_base + jn * 16));
                ldsm4t(bhi, b_base + off);
                ldsm4t(blo, b_base + (B_LO_OFF - B_HI_OFF) + off);
                #pragma unroll
                for (int mt = 0; mt < 2; mt++) {
                    mma16816(acc[mt][jn],     ahi[mt], bhi);
                    mma16816(acc[mt][jn],     ahi[mt], blo);
                    mma16816(acc[mt][jn],     alo[mt], bhi);
                    mma16816(acc[mt][jn + 1], ahi[mt], bhi + 2);
                    mma16816(acc[mt][jn + 1], ahi[mt], blo + 2);
                    mma16816(acc[mt][jn + 1], alo[mt], bhi + 2);
                }
            }
        }

        // ---- convert + store chunk c+1 into stage st^1
        if (c + 1 < CHUNKS) {
            char* stg = smem + (st ^ 1) * STAGE_BYTES;
            #pragma unroll
            for (int i = 0; i < 4; i++) {
                int idx = i * 512 + tid;
                {
                    int r = idx >> 4, c4 = idx & 15;
                    float lx, ly, lz, lw;
                    uint32_t h01 = split_pack_hi(avr[i].x, avr[i].y, lx, ly);
                    uint32_t h23 = split_pack_hi(avr[i].z, avr[i].w, lz, lw);
                    uint32_t off = sw_a((uint32_t)(r * 128 + c4 * 8));
                    *(uint2*)(stg + A_HI_OFF + off) = make_uint2(h01, h23);
                    *(uint2*)(stg + A_LO_OFF + off) = make_uint2(pack_bf16(lx, ly), pack_bf16(lz, lw));
                }
                {
                    int kr = idx >> 5, n4 = idx & 31;
                    float lx, ly, lz, lw;
                    uint32_t h01 = split_pack_hi(bvr[i].x, bvr[i].y, lx, ly);
                    uint32_t h23 = split_pack_hi(bvr[i].z, bvr[i].w, lz, lw);
                    uint32_t off = sw_b((uint32_t)(kr * 256 + n4 * 8));
                    *(uint2*)(stg + B_HI_OFF + off) = make_uint2(h01, h23);
                    *(uint2*)(stg + B_LO_OFF + off) = make_uint2(pack_bf16(lx, ly), pack_bf16(lz, lw));
                }
            }
        }
    }

    // ---- epilogue: bias + store
    const int er0 = row0 + warp_m * 32 + (lane >> 2);
    const int ec0 = col0 + warp_n * 32 + (lane & 3) * 2;
    #pragma unroll
    for (int mt = 0; mt < 2; mt++) {
        #pragma unroll
        for (int nt = 0; nt < 4; nt++) {
            const int col = ec0 + nt * 8;
            const float2 bb = *(const float2*)(bias + col);
            const int r0 = er0 + mt * 16;
            float2 o0, o1;
            o0.x = acc[mt][nt][0] + bb.x; o0.y = acc[mt][nt][1] + bb.y;
            o1.x = acc[mt][nt][2] + bb.x; o1.y = acc[mt][nt][3] + bb.y;
            *(float2*)(C + (size_t)r0 * GN + col)       = o0;
            *(float2*)(C + (size_t)(r0 + 8) * GN + col) = o1;
        }
    }
}

// ---------------------------------------------------------------------------
// Flash attention (fp32) — unchanged (tensorize next round)
// ---------------------------------------------------------------------------
__global__ __launch_bounds__(256) void attn_kernel(
    const float* __restrict__ Q, const float* __restrict__ K,
    const float* __restrict__ V, float* __restrict__ O)
{
    __shared__ float QT[64 * 64];
    __shared__ float KPT[64 * 64];
    __shared__ float Vs[64 * 64];

    const int tid = threadIdx.x;
    const int tx = tid & 15;
    const int ty = tid >> 4;

    const int lt = blockIdx.x & 31;
    const int h  = (blockIdx.x >> 5) & 15;
    const int b  = blockIdx.x >> 9;

    const float* Qbase = Q + ((size_t)(b * Ldim + lt * 64)) * Edim + h * Dh;
    const float* Kbase = K + (size_t)b * Sdim * Edim + h * Dh;
    const float* Vbase = V + (size_t)b * Sdim * Edim + h * Dh;

    for (int idx = tid; idx < 4096; idx += 256) {
        const int r = idx >> 6, d = idx & 63;
        QT[d * 64 + ((((r >> 2) ^ (d & 15)) << 2) | (r & 3))] =
            Qbase[(size_t)r * Edim + d];
    }

    float m_state[4], l_state[4], acc[4][4];
    #pragma unroll
    for (int i = 0; i < 4; i++) {
        m_state[i] = -1e30f;
        l_state[i] = 0.0f;
        #pragma unroll
        for (int j = 0; j < 4; j++) acc[i][j] = 0.0f;
    }

    const float scale = 0.125f;

    for (int sc = 0; sc < Sdim / 64; sc++) {
        const float* Kc = Kbase + (size_t)sc * 64 * Edim;
        const float* Vc = Vbase + (size_t)sc * 64 * Edim;

        __syncthreads();
        for (int idx = tid; idx < 4096; idx += 256) {
            const int s = idx >> 6, d = idx & 63;
            KPT[d * 64 + ((((s >> 2) ^ (d & 15)) << 2) | (s & 3))] =
                Kc[(size_t)s * Edim + d];
            Vs[idx] = Vc[(size_t)s * Edim + d];
        }
        __syncthreads();

        float p[4][4];
        #pragma unroll
        for (int i = 0; i < 4; i++)
            #pragma unroll
            for (int j = 0; j < 4; j++) p[i][j] = 0.0f;

        #pragma unroll 4
        for (int d = 0; d < 64; d++) {
            float4 aq = *(const float4*)&QT[d * 64 + ((ty ^ (d & 15)) << 2)];
            float4 bk = *(const float4*)&KPT[d * 64 + ((tx ^ (d & 15)) << 2)];
            float aa[4] = {aq.x, aq.y, aq.z, aq.w};
            float bb[4] = {bk.x, bk.y, bk.z, bk.w};
            #pragma unroll
            for (int i = 0; i < 4; i++)
                #pragma unroll
                for (int j = 0; j < 4; j++)
                    p[i][j] = fmaf(aa[i], bb[j], p[i][j]);
        }

        __syncthreads();

        #pragma unroll
        for (int i = 0; i < 4; i++) {
            float t0 = p[i][0] * scale, t1 = p[i][1] * scale;
            float t2 = p[i][2] * scale, t3 = p[i][3] * scale;
            float mx = fmaxf(fmaxf(t0, t1), fmaxf(t2, t3));
            #pragma unroll
            for (int o = 8; o >= 1; o >>= 1)
                mx = fmaxf(mx, __shfl_xor_sync(0xffffffffu, mx, o));
            const float m_new = fmaxf(m_state[i], mx);
            const float corr = __expf(m_state[i] - m_new);
            t0 = __expf(t0 - m_new); t1 = __expf(t1 - m_new);
            t2 = __expf(t2 - m_new); t3 = __expf(t3 - m_new);
            float rs = t0 + t1 + t2 + t3;
            #pragma unroll
            for (int o = 8; o >= 1; o >>= 1)
                rs += __shfl_xor_sync(0xffffffffu, rs, o);
            l_state[i] = l_state[i] * corr + rs;
            m_state[i] = m_new;
            #pragma unroll
            for (int j = 0; j < 4; j++) acc[i][j] *= corr;
            p[i][0] = t0; p[i][1] = t1; p[i][2] = t2; p[i][3] = t3;
        }

        #pragma unroll
        for (int j = 0; j < 4; j++) {
            const int c = tx * 4 + j;
            #pragma unroll
            for (int i = 0; i < 4; i++)
                KPT[c * 64 + (((ty ^ (c & 15)) << 2) | i)] = p[i][j];
        }
        __syncthreads();

        #pragma unroll 4
        for (int s = 0; s < 64; s++) {
            float4 ap = *(const float4*)&KPT[s * 64 + ((ty ^ (s & 15)) << 2)];
            float4 bv = *(const float4*)&Vs[s * 64 + tx * 4];
            float aa[4] = {ap.x, ap.y, ap.z, ap.w};
            float bb[4] = {bv.x, bv.y, bv.z, bv.w};
            #pragma unroll
            for (int i = 0; i < 4; i++)
                #pragma unroll
                for (int j = 0; j < 4; j++)
                    acc[i][j] = fmaf(aa[i], bb[j], acc[i][j]);
        }
    }

    #pragma unroll
    for (int i = 0; i < 4; i++) {
        const float inv = 1.0f / l_state[i];
        const int r = lt * 64 + ty * 4 + i;
        float4 o;
        o.x = acc[i][0] * inv; o.y = acc[i][1] * inv;
        o.z = acc[i][2] * inv; o.w = acc[i][3] * inv;
        *(float4*)(O + ((size_t)(b * Ldim + r)) * Edim + h * Dh + tx * 4) = o;
    }
}

// ---------------------------------------------------------------------------
extern "C" void kernel_launch(void* const* d_in, const int* in_sizes, int n_in,
                              void* d_out, int out_size)
{
    const float* x   = (const float*)d_in[0];
    const float* ctx = (const float*)d_in[1];
    const float* Wq  = (const float*)d_in[2];
    const float* bq  = (const float*)d_in[3];
    const float* Wk  = (const float*)d_in[4];
    const float* bk  = (const float*)d_in[5];
    const float* Wv  = (const float*)d_in[6];
    const float* bv  = (const float*)d_in[7];
    const float* Wp  = (const float*)d_in[8];
    const float* bp  = (const float*)d_in[9];
    float* out = (float*)d_out;

    float *Qb, *Kb, *Vb, *Ob;
    cudaGetSymbolAddress((void**)&Qb, g_Q);
    cudaGetSymbolAddress((void**)&Kb, g_K);
    cudaGetSymbolAddress((void**)&Vb, g_V);
    cudaGetSymbolAddress((void**)&Ob, g_O);

    cudaFuncSetAttribute(gemm_tc_kernel,
                         cudaFuncAttributeMaxDynamicSharedMemorySize,
                         GEMM_SMEM_TOTAL);

    dim3 gemm_grid(GN / BN, GM / BM);   // (8, 32)

    gemm_tc_kernel<<<gemm_grid, 512, GEMM_SMEM_TOTAL>>>(x,   Wq, bq, Qb);
    gemm_tc_kernel<<<gemm_grid, 512, GEMM_SMEM_TOTAL>>>(ctx, Wk, bk, Kb);
    gemm_tc_kernel<<<gemm_grid, 512, GEMM_SMEM_TOTAL>>>(ctx, Wv, bv, Vb);

    attn_kernel<<<Bdim * Hn * (Ldim / 64), 256>>>(Qb, Kb, Vb, Ob);

    gemm_tc_kernel<<<gemm_grid, 512, GEMM_SMEM_TOTAL>>>(Ob, Wp, bp, out);
}

// round 4
// speedup vs baseline: 2.5488x; 2.0034x over previous
#include <cuda_runtime.h>
#include <cuda_bf16.h>
#include <math.h>
#include <stdint.h>

#define Bdim 2
#define Ldim 2048
#define Sdim 2048
#define Edim 1024
#define Hn   16
#define Dh   64
#define Mrows 4096   // B*L = B*S

#define GM Mrows
#define GN Edim
#define GK Edim

// GEMM tiling
#define BM 128
#define BN 128
#define BK 64
#define CHUNKS (GK / BK)      // 16

// Scratch (module-load allocated, allowed)
__device__ float g_Q[(size_t)Mrows * Edim];
__device__ float g_K[(size_t)Mrows * Edim];
__device__ float g_V[(size_t)Mrows * Edim];
__device__ float g_O[(size_t)Mrows * Edim];

// ---------------------------------------------------------------------------
// helpers
// ---------------------------------------------------------------------------
__device__ __forceinline__ uint32_t smem_u32(const void* p) {
    uint32_t a;
    asm("{ .reg .u64 t; cvta.to.shared.u64 t, %1; cvt.u32.u64 %0, t; }"
        : "=r"(a) : "l"(p));
    return a;
}

__device__ __forceinline__ void ldsm4(uint32_t* r, uint32_t addr) {
    asm volatile("ldmatrix.sync.aligned.m8n8.x4.shared.b16 {%0,%1,%2,%3}, [%4];"
                 : "=r"(r[0]), "=r"(r[1]), "=r"(r[2]), "=r"(r[3]) : "r"(addr));
}
__device__ __forceinline__ void ldsm4t(uint32_t* r, uint32_t addr) {
    asm volatile("ldmatrix.sync.aligned.m8n8.x4.trans.shared.b16 {%0,%1,%2,%3}, [%4];"
                 : "=r"(r[0]), "=r"(r[1]), "=r"(r[2]), "=r"(r[3]) : "r"(addr));
}

__device__ __forceinline__ void mma16816(float* d, const uint32_t* a, const uint32_t* b) {
    asm volatile(
        "mma.sync.aligned.m16n8k16.row.col.f32.bf16.bf16.f32 "
        "{%0,%1,%2,%3}, {%4,%5,%6,%7}, {%8,%9}, {%0,%1,%2,%3};"
        : "+f"(d[0]), "+f"(d[1]), "+f"(d[2]), "+f"(d[3])
        : "r"(a[0]), "r"(a[1]), "r"(a[2]), "r"(a[3]), "r"(b[0]), "r"(b[1]));
}

__device__ __forceinline__ float ex2f(float x) {
    float y;
    asm("ex2.approx.f32 %0, %1;" : "=f"(y) : "f"(x));
    return y;
}

// split float pair into bf16 hi (packed) + lo floats
__device__ __forceinline__ uint32_t split_pack_hi(float a, float b, float& la, float& lb) {
    __nv_bfloat16 ha = __float2bfloat16_rn(a);
    __nv_bfloat16 hb = __float2bfloat16_rn(b);
    la = a - __bfloat162float(ha);
    lb = b - __bfloat162float(hb);
    return ((uint32_t)__bfloat16_as_ushort(hb) << 16) | (uint32_t)__bfloat16_as_ushort(ha);
}
__device__ __forceinline__ uint32_t pack_bf16(float a, float b) {
    __nv_bfloat16 ha = __float2bfloat16_rn(a);
    __nv_bfloat16 hb = __float2bfloat16_rn(b);
    return ((uint32_t)__bfloat16_as_ushort(hb) << 16) | (uint32_t)__bfloat16_as_ushort(ha);
}

// swizzles: 128B rows / 256B rows
__device__ __forceinline__ uint32_t sw_a(uint32_t off) { return off ^ ((off >> 3) & 0x70); }
__device__ __forceinline__ uint32_t sw_b(uint32_t off) { return off ^ ((off >> 4) & 0x70); }

// ===========================================================================
// GEMM (unchanged from round 3 — passing, ~100us each)
// ===========================================================================
#define A_HI_OFF    0
#define A_LO_OFF    16384
#define B_HI_OFF    32768
#define B_LO_OFF    49152
#define STAGE_BYTES 65536
#define GEMM_SMEM_TOTAL (2 * STAGE_BYTES)   // 131072

__global__ __launch_bounds__(512, 1) void gemm_tc_kernel(
    const float* __restrict__ A, const float* __restrict__ W,
    const float* __restrict__ bias, float* __restrict__ C)
{
    extern __shared__ char smem[];
    const uint32_t smem_base = smem_u32(smem);

    const int tid    = threadIdx.x;
    const int wid    = tid >> 5;
    const int lane   = tid & 31;
    const int warp_m = wid & 3;
    const int warp_n = wid >> 2;
    const int row0   = blockIdx.y * BM;
    const int col0   = blockIdx.x * BN;

    const int sub = lane >> 3;
    const int lr  = lane & 7;

    const int a_row_base = warp_m * 32 + (sub & 1) * 8 + lr;
    const int a_kb_base  = (sub >> 1) * 16;
    const int b_k_base  = (sub & 1) * 8 + lr;
    const int b_nb_base = (warp_n * 32 + (sub >> 1) * 8) * 2;

    float acc[2][4][4];
    #pragma unroll
    for (int mt = 0; mt < 2; mt++)
        #pragma unroll
        for (int nt = 0; nt < 4; nt++)
            #pragma unroll
            for (int q = 0; q < 4; q++) acc[mt][nt][q] = 0.0f;

    float4 avr[4], bvr[4];

    {
        #pragma unroll
        for (int i = 0; i < 4; i++) {
            int idx = i * 512 + tid;
            int r = idx >> 4, c4 = idx & 15;
            avr[i] = *(const float4*)(A + (size_t)(row0 + r) * GK + c4 * 4);
            int kr = idx >> 5, n4 = idx & 31;
            bvr[i] = *(const float4*)(W + (size_t)kr * GN + col0 + n4 * 4);
        }
        char* stg = smem;
        #pragma unroll
        for (int i = 0; i < 4; i++) {
            int idx = i * 512 + tid;
            {
                int r = idx >> 4, c4 = idx & 15;
                float lx, ly, lz, lw;
                uint32_t h01 = split_pack_hi(avr[i].x, avr[i].y, lx, ly);
                uint32_t h23 = split_pack_hi(avr[i].z, avr[i].w, lz, lw);
                uint32_t off = sw_a((uint32_t)(r * 128 + c4 * 8));
                *(uint2*)(stg + A_HI_OFF + off) = make_uint2(h01, h23);
                *(uint2*)(stg + A_LO_OFF + off) = make_uint2(pack_bf16(lx, ly), pack_bf16(lz, lw));
            }
            {
                int kr = idx >> 5, n4 = idx & 31;
                float lx, ly, lz, lw;
                uint32_t h01 = split_pack_hi(bvr[i].x, bvr[i].y, lx, ly);
                uint32_t h23 = split_pack_hi(bvr[i].z, bvr[i].w, lz, lw);
                uint32_t off = sw_b((uint32_t)(kr * 256 + n4 * 8));
                *(uint2*)(stg + B_HI_OFF + off) = make_uint2(h01, h23);
                *(uint2*)(stg + B_LO_OFF + off) = make_uint2(pack_bf16(lx, ly), pack_bf16(lz, lw));
            }
        }
    }

    for (int c = 0; c < CHUNKS; c++) {
        const int st = c & 1;
        const uint32_t a_base = smem_base + st * STAGE_BYTES;
        const uint32_t b_base = a_base + B_HI_OFF;

        __syncthreads();

        if (c + 1 < CHUNKS) {
            const int k0n = (c + 1) * BK;
            #pragma unroll
            for (int i = 0; i < 4; i++) {
                int idx = i * 512 + tid;
                int r = idx >> 4, c4 = idx & 15;
                avr[i] = *(const float4*)(A + (size_t)(row0 + r) * GK + k0n + c4 * 4);
                int kr = idx >> 5, n4 = idx & 31;
                bvr[i] = *(const float4*)(W + (size_t)(k0n + kr) * GN + col0 + n4 * 4);
            }
        }

        #pragma unroll
        for (int ks = 0; ks < 4; ks++) {
            uint32_t ahi[2][4], alo[2][4];
            #pragma unroll
            for (int mt = 0; mt < 2; mt++) {
                uint32_t off = sw_a((uint32_t)((a_row_base + mt * 16) * 128 + ks * 32 + a_kb_base));
                ldsm4(ahi[mt], a_base + A_HI_OFF + off);
                ldsm4(alo[mt], a_base + A_LO_OFF + off);
            }
            #pragma unroll
            for (int jn = 0; jn < 4; jn += 2) {
                uint32_t bhi[4], blo[4];
                uint32_t off = sw_b((uint32_t)((ks * 16 + b_k_base) * 256 + b_nb_base + jn * 16));
                ldsm4t(bhi, b_base + off);
                ldsm4t(blo, b_base + (B_LO_OFF - B_HI_OFF) + off);
                #pragma unroll
                for (int mt = 0; mt < 2; mt++) {
                    mma16816(acc[mt][jn],     ahi[mt], bhi);
                    mma16816(acc[mt][jn],     ahi[mt], blo);
                    mma16816(acc[mt][jn],     alo[mt], bhi);
                    mma16816(acc[mt][jn + 1], ahi[mt], bhi + 2);
                    mma16816(acc[mt][jn + 1], ahi[mt], blo + 2);
                    mma16816(acc[mt][jn + 1], alo[mt], bhi + 2);
                }
            }
        }

        if (c + 1 < CHUNKS) {
            char* stg = smem + (st ^ 1) * STAGE_BYTES;
            #pragma unroll
            for (int i = 0; i < 4; i++) {
                int idx = i * 512 + tid;
                {
                    int r = idx >> 4, c4 = idx & 15;
                    float lx, ly, lz, lw;
                    uint32_t h01 = split_pack_hi(avr[i].x, avr[i].y, lx, ly);
                    uint32_t h23 = split_pack_hi(avr[i].z, avr[i].w, lz, lw);
                    uint32_t off = sw_a((uint32_t)(r * 128 + c4 * 8));
                    *(uint2*)(stg + A_HI_OFF + off) = make_uint2(h01, h23);
                    *(uint2*)(stg + A_LO_OFF + off) = make_uint2(pack_bf16(lx, ly), pack_bf16(lz, lw));
                }
                {
                    int kr = idx >> 5, n4 = idx & 31;
                    float lx, ly, lz, lw;
                    uint32_t h01 = split_pack_hi(bvr[i].x, bvr[i].y, lx, ly);
                    uint32_t h23 = split_pack_hi(bvr[i].z, bvr[i].w, lz, lw);
                    uint32_t off = sw_b((uint32_t)(kr * 256 + n4 * 8));
                    *(uint2*)(stg + B_HI_OFF + off) = make_uint2(h01, h23);
                    *(uint2*)(stg + B_LO_OFF + off) = make_uint2(pack_bf16(lx, ly), pack_bf16(lz, lw));
                }
            }
        }
    }

    const int er0 = row0 + warp_m * 32 + (lane >> 2);
    const int ec0 = col0 + warp_n * 32 + (lane & 3) * 2;
    #pragma unroll
    for (int mt = 0; mt < 2; mt++) {
        #pragma unroll
        for (int nt = 0; nt < 4; nt++) {
            const int col = ec0 + nt * 8;
            const float2 bb = *(const float2*)(bias + col);
            const int r0 = er0 + mt * 16;
            float2 o0, o1;
            o0.x = acc[mt][nt][0] + bb.x; o0.y = acc[mt][nt][1] + bb.y;
            o1.x = acc[mt][nt][2] + bb.x; o1.y = acc[mt][nt][3] + bb.y;
            *(float2*)(C + (size_t)r0 * GN + col)       = o0;
            *(float2*)(C + (size_t)(r0 + 8) * GN + col) = o1;
        }
    }
}

// ===========================================================================
// Tensor-core flash attention (bf16x3 split, exp2 domain)
// 512 CTAs = B*H*(L/128). 256 threads = 8 warps; warp w owns query rows
// w*16..w*16+15. S chunked by 64, K/V double-buffered bf16 hi/lo in smem.
// Q (prescaled by 0.125*log2e) resident hi/lo in smem.
// SMEM: Qhi 16K | Qlo 16K | 2 stages x (Khi 8K | Klo 8K | Vhi 8K | Vlo 8K)
// ===========================================================================
#define ATT_Q_HI    0
#define ATT_Q_LO    16384
#define ATT_STAGE0  32768
#define ATT_STG_SZ  32768
#define ATT_K_HI    0
#define ATT_K_LO    8192
#define ATT_V_HI    16384
#define ATT_V_LO    24576
#define ATT_SMEM_TOTAL (ATT_STAGE0 + 2 * ATT_STG_SZ)  // 98304
#define SCHUNKS (Sdim / 64)   // 32

__global__ __launch_bounds__(256, 2) void attn_tc_kernel(
    const float* __restrict__ Q, const float* __restrict__ K,
    const float* __restrict__ V, float* __restrict__ O)
{
    extern __shared__ char smem[];
    const uint32_t smem_base = smem_u32(smem);

    const int tid  = threadIdx.x;
    const int wid  = tid >> 5;
    const int lane = tid & 31;
    const int sub  = lane >> 3;
    const int lr   = lane & 7;

    const int lt = blockIdx.x & 15;          // L tile (128 rows)
    const int h  = (blockIdx.x >> 4) & 15;
    const int b  = blockIdx.x >> 8;

    const float* Qbase = Q + ((size_t)(b * Ldim + lt * 128)) * Edim + h * Dh;
    const float* Kbase = K + (size_t)b * Sdim * Edim + h * Dh;
    const float* Vbase = V + (size_t)b * Sdim * Edim + h * Dh;

    const float QSCALE = 0.18033688f;   // 0.125 * log2(e)

    // ---- load Q (prescaled, split) into resident smem
    #pragma unroll
    for (int i = 0; i < 8; i++) {
        int idx = i * 256 + tid;
        int r = idx >> 4, c4 = idx & 15;
        float4 v = *(const float4*)(Qbase + (size_t)r * Edim + c4 * 4);
        v.x *= QSCALE; v.y *= QSCALE; v.z *= QSCALE; v.w *= QSCALE;
        float lx, ly, lz, lw;
        uint32_t h01 = split_pack_hi(v.x, v.y, lx, ly);
        uint32_t h23 = split_pack_hi(v.z, v.w, lz, lw);
        uint32_t off = sw_a((uint32_t)(r * 128 + c4 * 8));
        *(uint2*)(smem + ATT_Q_HI + off) = make_uint2(h01, h23);
        *(uint2*)(smem + ATT_Q_LO + off) = make_uint2(pack_bf16(lx, ly), pack_bf16(lz, lw));
    }

    // ---- prologue: load + convert chunk 0 into stage 0
    float4 kvr[4], vvr[4];
    #pragma unroll
    for (int i = 0; i < 4; i++) {
        int idx = i * 256 + tid;
        int s = idx >> 4, c4 = idx & 15;
        kvr[i] = *(const float4*)(Kbase + (size_t)s * Edim + c4 * 4);
        vvr[i] = *(const float4*)(Vbase + (size_t)s * Edim + c4 * 4);
    }
    {
        char* stg = smem + ATT_STAGE0;
        #pragma unroll
        for (int i = 0; i < 4; i++) {
            int idx = i * 256 + tid;
            int s = idx >> 4, c4 = idx & 15;
            uint32_t off = sw_a((uint32_t)(s * 128 + c4 * 8));
            float lx, ly, lz, lw;
            uint32_t h01 = split_pack_hi(kvr[i].x, kvr[i].y, lx, ly);
            uint32_t h23 = split_pack_hi(kvr[i].z, kvr[i].w, lz, lw);
            *(uint2*)(stg + ATT_K_HI + off) = make_uint2(h01, h23);
            *(uint2*)(stg + ATT_K_LO + off) = make_uint2(pack_bf16(lx, ly), pack_bf16(lz, lw));
            h01 = split_pack_hi(vvr[i].x, vvr[i].y, lx, ly);
            h23 = split_pack_hi(vvr[i].z, vvr[i].w, lz, lw);
            *(uint2*)(stg + ATT_V_HI + off) = make_uint2(h01, h23);
            *(uint2*)(stg + ATT_V_LO + off) = make_uint2(pack_bf16(lx, ly), pack_bf16(lz, lw));
        }
    }

    // persistent state
    float acc_o[8][4];
    #pragma unroll
    for (int nt = 0; nt < 8; nt++)
        #pragma unroll
        for (int q = 0; q < 4; q++) acc_o[nt][q] = 0.0f;
    float m0 = -1e30f, m1 = -1e30f, l0 = 0.0f, l1 = 0.0f;

    // ldmatrix address bases
    const int q_row = wid * 16 + (sub & 1) * 8 + lr;    // A frags (Q)
    const int q_kb  = (sub >> 1) * 16;
    const int k_row_off = ((lane >> 4) & 1) * 8 + lr;   // K non-trans b-frags
    const int k_kb      = ((lane >> 3) & 1) * 16;
    const int v_row_off = (sub & 1) * 8 + lr;           // V trans b-frags
    const int v_nb      = (sub >> 1) * 16;              // bytes

    for (int sc = 0; sc < SCHUNKS; sc++) {
        const uint32_t stg = smem_base + ATT_STAGE0 + (sc & 1) * ATT_STG_SZ;

        __syncthreads();   // stage stores visible; other-stage reads (sc-1) done

        // prefetch chunk sc+1
        if (sc + 1 < SCHUNKS) {
            const float* Kc = Kbase + (size_t)(sc + 1) * 64 * Edim;
            const float* Vc = Vbase + (size_t)(sc + 1) * 64 * Edim;
            #pragma unroll
            for (int i = 0; i < 4; i++) {
                int idx = i * 256 + tid;
                int s = idx >> 4, c4 = idx & 15;
                kvr[i] = *(const float4*)(Kc + (size_t)s * Edim + c4 * 4);
                vvr[i] = *(const float4*)(Vc + (size_t)s * Edim + c4 * 4);
            }
        }

        // ---- QK^T scores (16 rows x 64 cols per warp), bf16x3
        float acc_s[8][4];
        #pragma unroll
        for (int nt = 0; nt < 8; nt++)
            #pragma unroll
            for (int q = 0; q < 4; q++) acc_s[nt][q] = 0.0f;

        #pragma unroll
        for (int ks = 0; ks < 4; ks++) {
            uint32_t qhi[4], qlo[4];
            uint32_t qoff = sw_a((uint32_t)(q_row * 128 + ks * 32 + q_kb));
            ldsm4(qhi, smem_base + ATT_Q_HI + qoff);
            ldsm4(qlo, smem_base + ATT_Q_LO + qoff);
            #pragma unroll
            for (int jg = 0; jg < 4; jg++) {
                uint32_t khi[4], klo[4];
                uint32_t koff = sw_a((uint32_t)((jg * 16 + k_row_off) * 128 + ks * 32 + k_kb));
                ldsm4(khi, stg + ATT_K_HI + koff);
                ldsm4(klo, stg + ATT_K_LO + koff);
                mma16816(acc_s[jg * 2],     qhi, khi);
                mma16816(acc_s[jg * 2],     qhi, klo);
                mma16816(acc_s[jg * 2],     qlo, khi);
                mma16816(acc_s[jg * 2 + 1], qhi, khi + 2);
                mma16816(acc_s[jg * 2 + 1], qhi, klo + 2);
                mma16816(acc_s[jg * 2 + 1], qlo, khi + 2);
            }
        }

        // ---- online softmax (exp2 domain); rows r0=lane>>2, r1=r0+8
        float mx0 = acc_s[0][0], mx1 = acc_s[0][2];
        #pragma unroll
        for (int nt = 0; nt < 8; nt++) {
            mx0 = fmaxf(mx0, fmaxf(acc_s[nt][0], acc_s[nt][1]));
            mx1 = fmaxf(mx1, fmaxf(acc_s[nt][2], acc_s[nt][3]));
        }
        mx0 = fmaxf(mx0, __shfl_xor_sync(0xffffffffu, mx0, 1));
        mx0 = fmaxf(mx0, __shfl_xor_sync(0xffffffffu, mx0, 2));
        mx1 = fmaxf(mx1, __shfl_xor_sync(0xffffffffu, mx1, 1));
        mx1 = fmaxf(mx1, __shfl_xor_sync(0xffffffffu, mx1, 2));

        const float mn0 = fmaxf(m0, mx0);
        const float mn1 = fmaxf(m1, mx1);
        const float c0 = ex2f(m0 - mn0);
        const float c1 = ex2f(m1 - mn1);
        m0 = mn0; m1 = mn1;

        float s0 = 0.0f, s1 = 0.0f;
        #pragma unroll
        for (int nt = 0; nt < 8; nt++) {
            acc_s[nt][0] = ex2f(acc_s[nt][0] - mn0);
            acc_s[nt][1] = ex2f(acc_s[nt][1] - mn0);
            acc_s[nt][2] = ex2f(acc_s[nt][2] - mn1);
            acc_s[nt][3] = ex2f(acc_s[nt][3] - mn1);
            s0 += acc_s[nt][0] + acc_s[nt][1];
            s1 += acc_s[nt][2] + acc_s[nt][3];
        }
        s0 += __shfl_xor_sync(0xffffffffu, s0, 1);
        s0 += __shfl_xor_sync(0xffffffffu, s0, 2);
        s1 += __shfl_xor_sync(0xffffffffu, s1, 1);
        s1 += __shfl_xor_sync(0xffffffffu, s1, 2);
        l0 = l0 * c0 + s0;
        l1 = l1 * c1 + s1;

        #pragma unroll
        for (int nt = 0; nt < 8; nt++) {
            acc_o[nt][0] *= c0; acc_o[nt][1] *= c0;
            acc_o[nt][2] *= c1; acc_o[nt][3] *= c1;
        }

        // ---- PV: acc_o += P @ V (P frags from registers, bf16x3)
        #pragma unroll
        for (int ks = 0; ks < 4; ks++) {
            uint32_t phi[4], plo[4];
            float la, lb;
            phi[0] = split_pack_hi(acc_s[2 * ks][0],     acc_s[2 * ks][1],     la, lb);
            plo[0] = pack_bf16(la, lb);
            phi[1] = split_pack_hi(acc_s[2 * ks][2],     acc_s[2 * ks][3],     la, lb);
            plo[1] = pack_bf16(la, lb);
            phi[2] = split_pack_hi(acc_s[2 * ks + 1][0], acc_s[2 * ks + 1][1], la, lb);
            plo[2] = pack_bf16(la, lb);
            phi[3] = split_pack_hi(acc_s[2 * ks + 1][2], acc_s[2 * ks + 1][3], la, lb);
            plo[3] = pack_bf16(la, lb);
            #pragma unroll
            for (int jg = 0; jg < 4; jg++) {
                uint32_t vhi[4], vlo[4];
                uint32_t voff = sw_a((uint32_t)((ks * 16 + v_row_off) * 128 + jg * 32 + v_nb));
                ldsm4t(vhi, stg + ATT_V_HI + voff);
                ldsm4t(vlo, stg + ATT_V_LO + voff);
                mma16816(acc_o[jg * 2],     phi, vhi);
                mma16816(acc_o[jg * 2],     phi, vlo);
                mma16816(acc_o[jg * 2],     plo, vhi);
                mma16816(acc_o[jg * 2 + 1], phi, vhi + 2);
                mma16816(acc_o[jg * 2 + 1], phi, vlo + 2);
                mma16816(acc_o[jg * 2 + 1], plo, vhi + 2);
            }
        }

        // ---- convert + store chunk sc+1 into other stage
        if (sc + 1 < SCHUNKS) {
            char* nstg = smem + ATT_STAGE0 + ((sc + 1) & 1) * ATT_STG_SZ;
            #pragma unroll
            for (int i = 0; i < 4; i++) {
                int idx = i * 256 + tid;
                int s = idx >> 4, c4 = idx & 15;
                uint32_t off = sw_a((uint32_t)(s * 128 + c4 * 8));
                float lx, ly, lz, lw;
                uint32_t h01 = split_pack_hi(kvr[i].x, kvr[i].y, lx, ly);
                uint32_t h23 = split_pack_hi(kvr[i].z, kvr[i].w, lz, lw);
                *(uint2*)(nstg + ATT_K_HI + off) = make_uint2(h01, h23);
                *(uint2*)(nstg + ATT_K_LO + off) = make_uint2(pack_bf16(lx, ly), pack_bf16(lz, lw));
                h01 = split_pack_hi(vvr[i].x, vvr[i].y, lx, ly);
                h23 = split_pack_hi(vvr[i].z, vvr[i].w, lz, lw);
                *(uint2*)(nstg + ATT_V_HI + off) = make_uint2(h01, h23);
                *(uint2*)(nstg + ATT_V_LO + off) = make_uint2(pack_bf16(lx, ly), pack_bf16(lz, lw));
            }
        }
    }

    // ---- epilogue: normalize, store
    const float inv0 = 1.0f / l0;
    const float inv1 = 1.0f / l1;
    const int gr0 = b * Ldim + lt * 128 + wid * 16 + (lane >> 2);
    const int colb = h * Dh + (lane & 3) * 2;
    #pragma unroll
    for (int nt = 0; nt < 8; nt++) {
        float2 o0, o1;
        o0.x = acc_o[nt][0] * inv0; o0.y = acc_o[nt][1] * inv0;
        o1.x = acc_o[nt][2] * inv1; o1.y = acc_o[nt][3] * inv1;
        *(float2*)(O + (size_t)gr0 * Edim + colb + nt * 8)       = o0;
        *(float2*)(O + (size_t)(gr0 + 8) * Edim + colb + nt * 8) = o1;
    }
}

// ---------------------------------------------------------------------------
extern "C" void kernel_launch(void* const* d_in, const int* in_sizes, int n_in,
                              void* d_out, int out_size)
{
    const float* x   = (const float*)d_in[0];
    const float* ctx = (const float*)d_in[1];
    const float* Wq  = (const float*)d_in[2];
    const float* bq  = (const float*)d_in[3];
    const float* Wk  = (const float*)d_in[4];
    const float* bk  = (const float*)d_in[5];
    const float* Wv  = (const float*)d_in[6];
    const float* bv  = (const float*)d_in[7];
    const float* Wp  = (const float*)d_in[8];
    const float* bp  = (const float*)d_in[9];
    float* out = (float*)d_out;

    float *Qb, *Kb, *Vb, *Ob;
    cudaGetSymbolAddress((void**)&Qb, g_Q);
    cudaGetSymbolAddress((void**)&Kb, g_K);
    cudaGetSymbolAddress((void**)&Vb, g_V);
    cudaGetSymbolAddress((void**)&Ob, g_O);

    cudaFuncSetAttribute(gemm_tc_kernel,
                         cudaFuncAttributeMaxDynamicSharedMemorySize,
                         GEMM_SMEM_TOTAL);
    cudaFuncSetAttribute(attn_tc_kernel,
                         cudaFuncAttributeMaxDynamicSharedMemorySize,
                         ATT_SMEM_TOTAL);

    dim3 gemm_grid(GN / BN, GM / BM);   // (8, 32)

    gemm_tc_kernel<<<gemm_grid, 512, GEMM_SMEM_TOTAL>>>(x,   Wq, bq, Qb);
    gemm_tc_kernel<<<gemm_grid, 512, GEMM_SMEM_TOTAL>>>(ctx, Wk, bk, Kb);
    gemm_tc_kernel<<<gemm_grid, 512, GEMM_SMEM_TOTAL>>>(ctx, Wv, bv, Vb);

    attn_tc_kernel<<<Bdim * Hn * (Ldim / 128), 256, ATT_SMEM_TOTAL>>>(Qb, Kb, Vb, Ob);

    gemm_tc_kernel<<<gemm_grid, 512, GEMM_SMEM_TOTAL>>>(Ob, Wp, bp, out);
}

// round 5
// speedup vs baseline: 2.5490x; 1.0001x over previous
#include <cuda_runtime.h>
#include <cuda_bf16.h>
#include <math.h>
#include <stdint.h>

#define Bdim 2
#define Ldim 2048
#define Sdim 2048
#define Edim 1024
#define Hn   16
#define Dh   64
#define Mrows 4096   // B*L = B*S

#define GM Mrows
#define GN Edim
#define GK Edim

// GEMM tiling
#define BM 128
#define BN 128
#define BK 64
#define CHUNKS (GK / BK)      // 16

// Scratch (module-load allocated, allowed)
__device__ float g_Q[(size_t)Mrows * Edim];
__device__ float g_K[(size_t)Mrows * Edim];
__device__ float g_V[(size_t)Mrows * Edim];
__device__ float g_O[(size_t)Mrows * Edim];

// ---------------------------------------------------------------------------
// helpers
// ---------------------------------------------------------------------------
__device__ __forceinline__ uint32_t smem_u32(const void* p) {
    uint32_t a;
    asm("{ .reg .u64 t; cvta.to.shared.u64 t, %1; cvt.u32.u64 %0, t; }"
        : "=r"(a) : "l"(p));
    return a;
}

__device__ __forceinline__ void ldsm4(uint32_t* r, uint32_t addr) {
    asm volatile("ldmatrix.sync.aligned.m8n8.x4.shared.b16 {%0,%1,%2,%3}, [%4];"
                 : "=r"(r[0]), "=r"(r[1]), "=r"(r[2]), "=r"(r[3]) : "r"(addr));
}
__device__ __forceinline__ void ldsm4t(uint32_t* r, uint32_t addr) {
    asm volatile("ldmatrix.sync.aligned.m8n8.x4.trans.shared.b16 {%0,%1,%2,%3}, [%4];"
                 : "=r"(r[0]), "=r"(r[1]), "=r"(r[2]), "=r"(r[3]) : "r"(addr));
}

__device__ __forceinline__ void mma16816(float* d, const uint32_t* a, const uint32_t* b) {
    asm volatile(
        "mma.sync.aligned.m16n8k16.row.col.f32.bf16.bf16.f32 "
        "{%0,%1,%2,%3}, {%4,%5,%6,%7}, {%8,%9}, {%0,%1,%2,%3};"
        : "+f"(d[0]), "+f"(d[1]), "+f"(d[2]), "+f"(d[3])
        : "r"(a[0]), "r"(a[1]), "r"(a[2]), "r"(a[3]), "r"(b[0]), "r"(b[1]));
}

__device__ __forceinline__ float ex2f(float x) {
    float y;
    asm("ex2.approx.f32 %0, %1;" : "=f"(y) : "f"(x));
    return y;
}

// split float pair into bf16 hi (packed) + lo floats
__device__ __forceinline__ uint32_t split_pack_hi(float a, float b, float& la, float& lb) {
    __nv_bfloat16 ha = __float2bfloat16_rn(a);
    __nv_bfloat16 hb = __float2bfloat16_rn(b);
    la = a - __bfloat162float(ha);
    lb = b - __bfloat162float(hb);
    return ((uint32_t)__bfloat16_as_ushort(hb) << 16) | (uint32_t)__bfloat16_as_ushort(ha);
}
__device__ __forceinline__ uint32_t pack_bf16(float a, float b) {
    __nv_bfloat16 ha = __float2bfloat16_rn(a);
    __nv_bfloat16 hb = __float2bfloat16_rn(b);
    return ((uint32_t)__bfloat16_as_ushort(hb) << 16) | (uint32_t)__bfloat16_as_ushort(ha);
}

// swizzles: 128B rows / 256B rows
__device__ __forceinline__ uint32_t sw_a(uint32_t off) { return off ^ ((off >> 3) & 0x70); }
__device__ __forceinline__ uint32_t sw_b(uint32_t off) { return off ^ ((off >> 4) & 0x70); }

// ===========================================================================
// GEMM (unchanged from round 3 — passing, ~100us each)
// ===========================================================================
#define A_HI_OFF    0
#define A_LO_OFF    16384
#define B_HI_OFF    32768
#define B_LO_OFF    49152
#define STAGE_BYTES 65536
#define GEMM_SMEM_TOTAL (2 * STAGE_BYTES)   // 131072

__global__ __launch_bounds__(512, 1) void gemm_tc_kernel(
    const float* __restrict__ A, const float* __restrict__ W,
    const float* __restrict__ bias, float* __restrict__ C)
{
    extern __shared__ char smem[];
    const uint32_t smem_base = smem_u32(smem);

    const int tid    = threadIdx.x;
    const int wid    = tid >> 5;
    const int lane   = tid & 31;
    const int warp_m = wid & 3;
    const int warp_n = wid >> 2;
    const int row0   = blockIdx.y * BM;
    const int col0   = blockIdx.x * BN;

    const int sub = lane >> 3;
    const int lr  = lane & 7;

    const int a_row_base = warp_m * 32 + (sub & 1) * 8 + lr;
    const int a_kb_base  = (sub >> 1) * 16;
    const int b_k_base  = (sub & 1) * 8 + lr;
    const int b_nb_base = (warp_n * 32 + (sub >> 1) * 8) * 2;

    float acc[2][4][4];
    #pragma unroll
    for (int mt = 0; mt < 2; mt++)
        #pragma unroll
        for (int nt = 0; nt < 4; nt++)
            #pragma unroll
            for (int q = 0; q < 4; q++) acc[mt][nt][q] = 0.0f;

    float4 avr[4], bvr[4];

    {
        #pragma unroll
        for (int i = 0; i < 4; i++) {
            int idx = i * 512 + tid;
            int r = idx >> 4, c4 = idx & 15;
            avr[i] = *(const float4*)(A + (size_t)(row0 + r) * GK + c4 * 4);
            int kr = idx >> 5, n4 = idx & 31;
            bvr[i] = *(const float4*)(W + (size_t)kr * GN + col0 + n4 * 4);
        }
        char* stg = smem;
        #pragma unroll
        for (int i = 0; i < 4; i++) {
            int idx = i * 512 + tid;
            {
                int r = idx >> 4, c4 = idx & 15;
                float lx, ly, lz, lw;
                uint32_t h01 = split_pack_hi(avr[i].x, avr[i].y, lx, ly);
                uint32_t h23 = split_pack_hi(avr[i].z, avr[i].w, lz, lw);
                uint32_t off = sw_a((uint32_t)(r * 128 + c4 * 8));
                *(uint2*)(stg + A_HI_OFF + off) = make_uint2(h01, h23);
                *(uint2*)(stg + A_LO_OFF + off) = make_uint2(pack_bf16(lx, ly), pack_bf16(lz, lw));
            }
            {
                int kr = idx >> 5, n4 = idx & 31;
                float lx, ly, lz, lw;
                uint32_t h01 = split_pack_hi(bvr[i].x, bvr[i].y, lx, ly);
                uint32_t h23 = split_pack_hi(bvr[i].z, bvr[i].w, lz, lw);
                uint32_t off = sw_b((uint32_t)(kr * 256 + n4 * 8));
                *(uint2*)(stg + B_HI_OFF + off) = make_uint2(h01, h23);
                *(uint2*)(stg + B_LO_OFF + off) = make_uint2(pack_bf16(lx, ly), pack_bf16(lz, lw));
            }
        }
    }

    for (int c = 0; c < CHUNKS; c++) {
        const int st = c & 1;
        const uint32_t a_base = smem_base + st * STAGE_BYTES;
        const uint32_t b_base = a_base + B_HI_OFF;

        __syncthreads();

        if (c + 1 < CHUNKS) {
            const int k0n = (c + 1) * BK;
            #pragma unroll
            for (int i = 0; i < 4; i++) {
                int idx = i * 512 + tid;
                int r = idx >> 4, c4 = idx & 15;
                avr[i] = *(const float4*)(A + (size_t)(row0 + r) * GK + k0n + c4 * 4);
                int kr = idx >> 5, n4 = idx & 31;
                bvr[i] = *(const float4*)(W + (size_t)(k0n + kr) * GN + col0 + n4 * 4);
            }
        }

        #pragma unroll
        for (int ks = 0; ks < 4; ks++) {
            uint32_t ahi[2][4], alo[2][4];
            #pragma unroll
            for (int mt = 0; mt < 2; mt++) {
                uint32_t off = sw_a((uint32_t)((a_row_base + mt * 16) * 128 + ks * 32 + a_kb_base));
                ldsm4(ahi[mt], a_base + A_HI_OFF + off);
                ldsm4(alo[mt], a_base + A_LO_OFF + off);
            }
            #pragma unroll
            for (int jn = 0; jn < 4; jn += 2) {
                uint32_t bhi[4], blo[4];
                uint32_t off = sw_b((uint32_t)((ks * 16 + b_k_base) * 256 + b_nb_base + jn * 16));
                ldsm4t(bhi, b_base + off);
                ldsm4t(blo, b_base + (B_LO_OFF - B_HI_OFF) + off);
                #pragma unroll
                for (int mt = 0; mt < 2; mt++) {
                    mma16816(acc[mt][jn],     ahi[mt], bhi);
                    mma16816(acc[mt][jn],     ahi[mt], blo);
                    mma16816(acc[mt][jn],     alo[mt], bhi);
                    mma16816(acc[mt][jn + 1], ahi[mt], bhi + 2);
                    mma16816(acc[mt][jn + 1], ahi[mt], blo + 2);
                    mma16816(acc[mt][jn + 1], alo[mt], bhi + 2);
                }
            }
        }

        if (c + 1 < CHUNKS) {
            char* stg = smem + (st ^ 1) * STAGE_BYTES;
            #pragma unroll
            for (int i = 0; i < 4; i++) {
                int idx = i * 512 + tid;
                {
                    int r = idx >> 4, c4 = idx & 15;
                    float lx, ly, lz, lw;
                    uint32_t h01 = split_pack_hi(avr[i].x, avr[i].y, lx, ly);
                    uint32_t h23 = split_pack_hi(avr[i].z, avr[i].w, lz, lw);
                    uint32_t off = sw_a((uint32_t)(r * 128 + c4 * 8));
                    *(uint2*)(stg + A_HI_OFF + off) = make_uint2(h01, h23);
                    *(uint2*)(stg + A_LO_OFF + off) = make_uint2(pack_bf16(lx, ly), pack_bf16(lz, lw));
                }
                {
                    int kr = idx >> 5, n4 = idx & 31;
                    float lx, ly, lz, lw;
                    uint32_t h01 = split_pack_hi(bvr[i].x, bvr[i].y, lx, ly);
                    uint32_t h23 = split_pack_hi(bvr[i].z, bvr[i].w, lz, lw);
                    uint32_t off = sw_b((uint32_t)(kr * 256 + n4 * 8));
                    *(uint2*)(stg + B_HI_OFF + off) = make_uint2(h01, h23);
                    *(uint2*)(stg + B_LO_OFF + off) = make_uint2(pack_bf16(lx, ly), pack_bf16(lz, lw));
                }
            }
        }
    }

    const int er0 = row0 + warp_m * 32 + (lane >> 2);
    const int ec0 = col0 + warp_n * 32 + (lane & 3) * 2;
    #pragma unroll
    for (int mt = 0; mt < 2; mt++) {
        #pragma unroll
        for (int nt = 0; nt < 4; nt++) {
            const int col = ec0 + nt * 8;
            const float2 bb = *(const float2*)(bias + col);
            const int r0 = er0 + mt * 16;
            float2 o0, o1;
            o0.x = acc[mt][nt][0] + bb.x; o0.y = acc[mt][nt][1] + bb.y;
            o1.x = acc[mt][nt][2] + bb.x; o1.y = acc[mt][nt][3] + bb.y;
            *(float2*)(C + (size_t)r0 * GN + col)       = o0;
            *(float2*)(C + (size_t)(r0 + 8) * GN + col) = o1;
        }
    }
}

// ===========================================================================
// Tensor-core flash attention (bf16x3 split, exp2 domain)
// 512 CTAs = B*H*(L/128). 256 threads = 8 warps; warp w owns query rows
// w*16..w*16+15. S chunked by 64, K/V double-buffered bf16 hi/lo in smem.
// Q (prescaled by 0.125*log2e) resident hi/lo in smem.
// SMEM: Qhi 16K | Qlo 16K | 2 stages x (Khi 8K | Klo 8K | Vhi 8K | Vlo 8K)
// ===========================================================================
#define ATT_Q_HI    0
#define ATT_Q_LO    16384
#define ATT_STAGE0  32768
#define ATT_STG_SZ  32768
#define ATT_K_HI    0
#define ATT_K_LO    8192
#define ATT_V_HI    16384
#define ATT_V_LO    24576
#define ATT_SMEM_TOTAL (ATT_STAGE0 + 2 * ATT_STG_SZ)  // 98304
#define SCHUNKS (Sdim / 64)   // 32

__global__ __launch_bounds__(256, 2) void attn_tc_kernel(
    const float* __restrict__ Q, const float* __restrict__ K,
    const float* __restrict__ V, float* __restrict__ O)
{
    extern __shared__ char smem[];
    const uint32_t smem_base = smem_u32(smem);

    const int tid  = threadIdx.x;
    const int wid  = tid >> 5;
    const int lane = tid & 31;
    const int sub  = lane >> 3;
    const int lr   = lane & 7;

    const int lt = blockIdx.x & 15;          // L tile (128 rows)
    const int h  = (blockIdx.x >> 4) & 15;
    const int b  = blockIdx.x >> 8;

    const float* Qbase = Q + ((size_t)(b * Ldim + lt * 128)) * Edim + h * Dh;
    const float* Kbase = K + (size_t)b * Sdim * Edim + h * Dh;
    const float* Vbase = V + (size_t)b * Sdim * Edim + h * Dh;

    const float QSCALE = 0.18033688f;   // 0.125 * log2(e)

    // ---- load Q (prescaled, split) into resident smem
    #pragma unroll
    for (int i = 0; i < 8; i++) {
        int idx = i * 256 + tid;
        int r = idx >> 4, c4 = idx & 15;
        float4 v = *(const float4*)(Qbase + (size_t)r * Edim + c4 * 4);
        v.x *= QSCALE; v.y *= QSCALE; v.z *= QSCALE; v.w *= QSCALE;
        float lx, ly, lz, lw;
        uint32_t h01 = split_pack_hi(v.x, v.y, lx, ly);
        uint32_t h23 = split_pack_hi(v.z, v.w, lz, lw);
        uint32_t off = sw_a((uint32_t)(r * 128 + c4 * 8));
        *(uint2*)(smem + ATT_Q_HI + off) = make_uint2(h01, h23);
        *(uint2*)(smem + ATT_Q_LO + off) = make_uint2(pack_bf16(lx, ly), pack_bf16(lz, lw));
    }

    // ---- prologue: load + convert chunk 0 into stage 0
    float4 kvr[4], vvr[4];
    #pragma unroll
    for (int i = 0; i < 4; i++) {
        int idx = i * 256 + tid;
        int s = idx >> 4, c4 = idx & 15;
        kvr[i] = *(const float4*)(Kbase + (size_t)s * Edim + c4 * 4);
        vvr[i] = *(const float4*)(Vbase + (size_t)s * Edim + c4 * 4);
    }
    {
        char* stg = smem + ATT_STAGE0;
        #pragma unroll
        for (int i = 0; i < 4; i++) {
            int idx = i * 256 + tid;
            int s = idx >> 4, c4 = idx & 15;
            uint32_t off = sw_a((uint32_t)(s * 128 + c4 * 8));
            float lx, ly, lz, lw;
            uint32_t h01 = split_pack_hi(kvr[i].x, kvr[i].y, lx, ly);
            uint32_t h23 = split_pack_hi(kvr[i].z, kvr[i].w, lz, lw);
            *(uint2*)(stg + ATT_K_HI + off) = make_uint2(h01, h23);
            *(uint2*)(stg + ATT_K_LO + off) = make_uint2(pack_bf16(lx, ly), pack_bf16(lz, lw));
            h01 = split_pack_hi(vvr[i].x, vvr[i].y, lx, ly);
            h23 = split_pack_hi(vvr[i].z, vvr[i].w, lz, lw);
            *(uint2*)(stg + ATT_V_HI + off) = make_uint2(h01, h23);
            *(uint2*)(stg + ATT_V_LO + off) = make_uint2(pack_bf16(lx, ly), pack_bf16(lz, lw));
        }
    }

    // persistent state
    float acc_o[8][4];
    #pragma unroll
    for (int nt = 0; nt < 8; nt++)
        #pragma unroll
        for (int q = 0; q < 4; q++) acc_o[nt][q] = 0.0f;
    float m0 = -1e30f, m1 = -1e30f, l0 = 0.0f, l1 = 0.0f;

    // ldmatrix address bases
    const int q_row = wid * 16 + (sub & 1) * 8 + lr;    // A frags (Q)
    const int q_kb  = (sub >> 1) * 16;
    const int k_row_off = ((lane >> 4) & 1) * 8 + lr;   // K non-trans b-frags
    const int k_kb      = ((lane >> 3) & 1) * 16;
    const int v_row_off = (sub & 1) * 8 + lr;           // V trans b-frags
    const int v_nb      = (sub >> 1) * 16;              // bytes

    for (int sc = 0; sc < SCHUNKS; sc++) {
        const uint32_t stg = smem_base + ATT_STAGE0 + (sc & 1) * ATT_STG_SZ;

        __syncthreads();   // stage stores visible; other-stage reads (sc-1) done

        // prefetch chunk sc+1
        if (sc + 1 < SCHUNKS) {
            const float* Kc = Kbase + (size_t)(sc + 1) * 64 * Edim;
            const float* Vc = Vbase + (size_t)(sc + 1) * 64 * Edim;
            #pragma unroll
            for (int i = 0; i < 4; i++) {
                int idx = i * 256 + tid;
                int s = idx >> 4, c4 = idx & 15;
                kvr[i] = *(const float4*)(Kc + (size_t)s * Edim + c4 * 4);
                vvr[i] = *(const float4*)(Vc + (size_t)s * Edim + c4 * 4);
            }
        }

        // ---- QK^T scores (16 rows x 64 cols per warp), bf16x3
        float acc_s[8][4];
        #pragma unroll
        for (int nt = 0; nt < 8; nt++)
            #pragma unroll
            for (int q = 0; q < 4; q++) acc_s[nt][q] = 0.0f;

        #pragma unroll
        for (int ks = 0; ks < 4; ks++) {
            uint32_t qhi[4], qlo[4];
            uint32_t qoff = sw_a((uint32_t)(q_row * 128 + ks * 32 + q_kb));
            ldsm4(qhi, smem_base + ATT_Q_HI + qoff);
            ldsm4(qlo, smem_base + ATT_Q_LO + qoff);
            #pragma unroll
            for (int jg = 0; jg < 4; jg++) {
                uint32_t khi[4], klo[4];
                uint32_t koff = sw_a((uint32_t)((jg * 16 + k_row_off) * 128 + ks * 32 + k_kb));
                ldsm4(khi, stg + ATT_K_HI + koff);
                ldsm4(klo, stg + ATT_K_LO + koff);
                mma16816(acc_s[jg * 2],     qhi, khi);
                mma16816(acc_s[jg * 2],     qhi, klo);
                mma16816(acc_s[jg * 2],     qlo, khi);
                mma16816(acc_s[jg * 2 + 1], qhi, khi + 2);
                mma16816(acc_s[jg * 2 + 1], qhi, klo + 2);
                mma16816(acc_s[jg * 2 + 1], qlo, khi + 2);
            }
        }

        // ---- online softmax (exp2 domain); rows r0=lane>>2, r1=r0+8
        float mx0 = acc_s[0][0], mx1 = acc_s[0][2];
        #pragma unroll
        for (int nt = 0; nt < 8; nt++) {
            mx0 = fmaxf(mx0, fmaxf(acc_s[nt][0], acc_s[nt][1]));
            mx1 = fmaxf(mx1, fmaxf(acc_s[nt][2], acc_s[nt][3]));
        }
        mx0 = fmaxf(mx0, __shfl_xor_sync(0xffffffffu, mx0, 1));
        mx0 = fmaxf(mx0, __shfl_xor_sync(0xffffffffu, mx0, 2));
        mx1 = fmaxf(mx1, __shfl_xor_sync(0xffffffffu, mx1, 1));
        mx1 = fmaxf(mx1, __shfl_xor_sync(0xffffffffu, mx1, 2));

        const float mn0 = fmaxf(m0, mx0);
        const float mn1 = fmaxf(m1, mx1);
        const float c0 = ex2f(m0 - mn0);
        const float c1 = ex2f(m1 - mn1);
        m0 = mn0; m1 = mn1;

        float s0 = 0.0f, s1 = 0.0f;
        #pragma unroll
        for (int nt = 0; nt < 8; nt++) {
            acc_s[nt][0] = ex2f(acc_s[nt][0] - mn0);
            acc_s[nt][1] = ex2f(acc_s[nt][1] - mn0);
            acc_s[nt][2] = ex2f(acc_s[nt][2] - mn1);
            acc_s[nt][3] = ex2f(acc_s[nt][3] - mn1);
            s0 += acc_s[nt][0] + acc_s[nt][1];
            s1 += acc_s[nt][2] + acc_s[nt][3];
        }
        s0 += __shfl_xor_sync(0xffffffffu, s0, 1);
        s0 += __shfl_xor_sync(0xffffffffu, s0, 2);
        s1 += __shfl_xor_sync(0xffffffffu, s1, 1);
        s1 += __shfl_xor_sync(0xffffffffu, s1, 2);
        l0 = l0 * c0 + s0;
        l1 = l1 * c1 + s1;

        #pragma unroll
        for (int nt = 0; nt < 8; nt++) {
            acc_o[nt][0] *= c0; acc_o[nt][1] *= c0;
            acc_o[nt][2] *= c1; acc_o[nt][3] *= c1;
        }

        // ---- PV: acc_o += P @ V (P frags from registers, bf16x3)
        #pragma unroll
        for (int ks = 0; ks < 4; ks++) {
            uint32_t phi[4], plo[4];
            float la, lb;
            phi[0] = split_pack_hi(acc_s[2 * ks][0],     acc_s[2 * ks][1],     la, lb);
            plo[0] = pack_bf16(la, lb);
            phi[1] = split_pack_hi(acc_s[2 * ks][2],     acc_s[2 * ks][3],     la, lb);
            plo[1] = pack_bf16(la, lb);
            phi[2] = split_pack_hi(acc_s[2 * ks + 1][0], acc_s[2 * ks + 1][1], la, lb);
            plo[2] = pack_bf16(la, lb);
            phi[3] = split_pack_hi(acc_s[2 * ks + 1][2], acc_s[2 * ks + 1][3], la, lb);
            plo[3] = pack_bf16(la, lb);
            #pragma unroll
            for (int jg = 0; jg < 4; jg++) {
                uint32_t vhi[4], vlo[4];
                uint32_t voff = sw_a((uint32_t)((ks * 16 + v_row_off) * 128 + jg * 32 + v_nb));
                ldsm4t(vhi, stg + ATT_V_HI + voff);
                ldsm4t(vlo, stg + ATT_V_LO + voff);
                mma16816(acc_o[jg * 2],     phi, vhi);
                mma16816(acc_o[jg * 2],     phi, vlo);
                mma16816(acc_o[jg * 2],     plo, vhi);
                mma16816(acc_o[jg * 2 + 1], phi, vhi + 2);
                mma16816(acc_o[jg * 2 + 1], phi, vlo + 2);
                mma16816(acc_o[jg * 2 + 1], plo, vhi + 2);
            }
        }

        // ---- convert + store chunk sc+1 into other stage
        if (sc + 1 < SCHUNKS) {
            char* nstg = smem + ATT_STAGE0 + ((sc + 1) & 1) * ATT_STG_SZ;
            #pragma unroll
            for (int i = 0; i < 4; i++) {
                int idx = i * 256 + tid;
                int s = idx >> 4, c4 = idx & 15;
                uint32_t off = sw_a((uint32_t)(s * 128 + c4 * 8));
                float lx, ly, lz, lw;
                uint32_t h01 = split_pack_hi(kvr[i].x, kvr[i].y, lx, ly);
                uint32_t h23 = split_pack_hi(kvr[i].z, kvr[i].w, lz, lw);
                *(uint2*)(nstg + ATT_K_HI + off) = make_uint2(h01, h23);
                *(uint2*)(nstg + ATT_K_LO + off) = make_uint2(pack_bf16(lx, ly), pack_bf16(lz, lw));
                h01 = split_pack_hi(vvr[i].x, vvr[i].y, lx, ly);
                h23 = split_pack_hi(vvr[i].z, vvr[i].w, lz, lw);
                *(uint2*)(nstg + ATT_V_HI + off) = make_uint2(h01, h23);
                *(uint2*)(nstg + ATT_V_LO + off) = make_uint2(pack_bf16(lx, ly), pack_bf16(lz, lw));
            }
        }
    }

    // ---- epilogue: normalize, store
    const float inv0 = 1.0f / l0;
    const float inv1 = 1.0f / l1;
    const int gr0 = b * Ldim + lt * 128 + wid * 16 + (lane >> 2);
    const int colb = h * Dh + (lane & 3) * 2;
    #pragma unroll
    for (int nt = 0; nt < 8; nt++) {
        float2 o0, o1;
        o0.x = acc_o[nt][0] * inv0; o0.y = acc_o[nt][1] * inv0;
        o1.x = acc_o[nt][2] * inv1; o1.y = acc_o[nt][3] * inv1;
        *(float2*)(O + (size_t)gr0 * Edim + colb + nt * 8)       = o0;
        *(float2*)(O + (size_t)(gr0 + 8) * Edim + colb + nt * 8) = o1;
    }
}

// ---------------------------------------------------------------------------
extern "C" void kernel_launch(void* const* d_in, const int* in_sizes, int n_in,
                              void* d_out, int out_size)
{
    const float* x   = (const float*)d_in[0];
    const float* ctx = (const float*)d_in[1];
    const float* Wq  = (const float*)d_in[2];
    const float* bq  = (const float*)d_in[3];
    const float* Wk  = (const float*)d_in[4];
    const float* bk  = (const float*)d_in[5];
    const float* Wv  = (const float*)d_in[6];
    const float* bv  = (const float*)d_in[7];
    const float* Wp  = (const float*)d_in[8];
    const float* bp  = (const float*)d_in[9];
    float* out = (float*)d_out;

    float *Qb, *Kb, *Vb, *Ob;
    cudaGetSymbolAddress((void**)&Qb, g_Q);
    cudaGetSymbolAddress((void**)&Kb, g_K);
    cudaGetSymbolAddress((void**)&Vb, g_V);
    cudaGetSymbolAddress((void**)&Ob, g_O);

    cudaFuncSetAttribute(gemm_tc_kernel,
                         cudaFuncAttributeMaxDynamicSharedMemorySize,
                         GEMM_SMEM_TOTAL);
    cudaFuncSetAttribute(attn_tc_kernel,
                         cudaFuncAttributeMaxDynamicSharedMemorySize,
                         ATT_SMEM_TOTAL);

    dim3 gemm_grid(GN / BN, GM / BM);   // (8, 32)

    gemm_tc_kernel<<<gemm_grid, 512, GEMM_SMEM_TOTAL>>>(x,   Wq, bq, Qb);
    gemm_tc_kernel<<<gemm_grid, 512, GEMM_SMEM_TOTAL>>>(ctx, Wk, bk, Kb);
    gemm_tc_kernel<<<gemm_grid, 512, GEMM_SMEM_TOTAL>>>(ctx, Wv, bv, Vb);

    attn_tc_kernel<<<Bdim * Hn * (Ldim / 128), 256, ATT_SMEM_TOTAL>>>(Qb, Kb, Vb, Ob);

    gemm_tc_kernel<<<gemm_grid, 512, GEMM_SMEM_TOTAL>>>(Ob, Wp, bp, out);
}